// round 2
// baseline (speedup 1.0000x reference)
#include <cuda_runtime.h>
#include <stdint.h>
#include <stddef.h>

#define BB 32768
#define MM 8192
#define GG 128
#define NCELL (GG*GG)

static __device__ __forceinline__ float f_inf() { return __int_as_float(0x7f800000); }

// ---------------- scratch (device globals; no allocation allowed) ----------------
__device__ float  g_X0p[BB*80];     // padded knn_feat (66 -> 80, zero pad)
__device__ float  g_X1[BB*128];
__device__ float  g_X2[BB*256];
__device__ float  g_X3[BB*512];
__device__ float  g_X4[BB*128];
__device__ float  g_X5[BB*64];
__device__ float  g_psum[256*512];  // per-rowblock column sums (max N=512)
__device__ float  g_psq [256*512];
__device__ float  g_scale[512];
__device__ float  g_shift[512];
__device__ int    g_cellCount[NCELL];
__device__ int    g_cellFill [NCELL];
__device__ int    g_cellStart[NCELL+1];
__device__ float4 g_packed[MM];     // (mx, my, mx^2+my^2, orig_idx)
__device__ float  g_W1p[80*128];    // zero-padded w1

// ---------------- grid build ----------------
__global__ void zero_cells_kernel() {
    int i = blockIdx.x*blockDim.x + threadIdx.x;
    if (i < NCELL) { g_cellCount[i] = 0; g_cellFill[i] = 0; }
}

__device__ __forceinline__ int cell_of(float v) {
    const float GMINF = -6.0f;
    const float INVH  = GG / 12.0f;
    int c = (int)floorf((v - GMINF) * INVH);
    return min(max(c, 0), GG-1);
}

__global__ void count_kernel(const float* __restrict__ mc) {
    int i = blockIdx.x*blockDim.x + threadIdx.x;
    if (i >= MM) return;
    int cx = cell_of(mc[2*i]);
    int cy = cell_of(mc[2*i+1]);
    atomicAdd(&g_cellCount[cy*GG + cx], 1);
}

__global__ void scan_kernel() {
    __shared__ int sums[256];
    int t = threadIdx.x;
    const int per = NCELL / 256;
    int base = t * per;
    int s = 0;
    for (int i = 0; i < per; i++) s += g_cellCount[base + i];
    sums[t] = s;
    __syncthreads();
    if (t == 0) {
        int acc = 0;
        for (int i = 0; i < 256; i++) { int v = sums[i]; sums[i] = acc; acc += v; }
    }
    __syncthreads();
    int off = sums[t];
    for (int i = 0; i < per; i++) { int v = g_cellCount[base + i]; g_cellStart[base + i] = off; off += v; }
    if (t == 255) g_cellStart[NCELL] = off;
}

__global__ void scatter_kernel(const float* __restrict__ mc) {
    int i = blockIdx.x*blockDim.x + threadIdx.x;
    if (i >= MM) return;
    float x = mc[2*i], y = mc[2*i+1];
    int cx = cell_of(x), cy = cell_of(y);
    int c = cy*GG + cx;
    int slot = g_cellStart[c] + atomicAdd(&g_cellFill[c], 1);
    // sm = rn(rn(x*x) + rn(y*y))  -- matches XLA elementwise square + reduce (no fma)
    float sm = __fadd_rn(__fmul_rn(x, x), __fmul_rn(y, y));
    g_packed[slot] = make_float4(x, y, sm, __int_as_float(i));
}

__global__ void padw1_kernel(const float* __restrict__ w1) {
    int i = blockIdx.x*blockDim.x + threadIdx.x;
    if (i >= 80*128) return;
    int row = i / 128, col = i % 128;
    g_W1p[i] = (row < 66) ? w1[row*128 + col] : 0.0f;
}

// ---------------- KNN ----------------
// Maintains a sorted (d2, idx) top-16 in registers. Comparator (d2, then idx)
// matches jax.lax.top_k tie-breaking and makes the result independent of the
// (nondeterministic) scan order within cells.
// d2 replicates the reference gemm's rounding: dot = fma(p1,m1, rn(p0*m0)),
// d2 = rn(rn(sp+sm) - 2*dot).
#define SCAN_RANGE(S_, E_)                                                        \
    for (int j_ = (S_); j_ < (E_); j_++) {                                        \
        float4 v_ = g_packed[j_];                                                 \
        float dot_ = __fmaf_rn(py, v_.y, __fmul_rn(px, v_.x));                    \
        float d2_  = __fmaf_rn(dot_, -2.0f, __fadd_rn(sp, v_.z));                 \
        int   mi_  = __float_as_int(v_.w);                                        \
        if (d2_ < key[15] || (d2_ == key[15] && mi_ < id[15])) {                  \
            float ck_ = d2_; int ci_ = mi_;                                       \
            _Pragma("unroll")                                                     \
            for (int t2_ = 0; t2_ < 16; t2_++) {                                  \
                bool sw_ = (ck_ < key[t2_]) || (ck_ == key[t2_] && ci_ < id[t2_]);\
                float tk_ = key[t2_]; int ti_ = id[t2_];                          \
                if (sw_) { key[t2_] = ck_; id[t2_] = ci_; ck_ = tk_; ci_ = ti_; } \
            }                                                                     \
        }                                                                         \
    }

__global__ void __launch_bounds__(256) knn_kernel(
    const float* __restrict__ pos, const float* __restrict__ mc,
    const float* __restrict__ mv, float* __restrict__ outKnn)
{
    const float GMINF = -6.0f;
    const float HCELL = 12.0f / GG;
    // Absolute safety margin: |formula_d2 - true_d2| <= (|p|+|m|)^2 * 2^-23
    // ~ 1.7e-5 here; use 1e-4 so the exact-geometry stop bound provably covers
    // formula-rounded candidates just outside the scanned box.
    const float MARGIN = 1e-4f;
    int q = blockIdx.x*blockDim.x + threadIdx.x;
    if (q >= BB) return;
    float px = pos[2*q], py = pos[2*q+1];
    float sp = __fadd_rn(__fmul_rn(px, px), __fmul_rn(py, py));

    float key[16]; int id[16];
#pragma unroll
    for (int i = 0; i < 16; i++) { key[i] = f_inf(); id[i] = 0x7fffffff; }

    int cx = cell_of(px), cy = cell_of(py);

    for (int R = 0;; R++) {
        int xlo = cx - R, xhi = cx + R, ylo = cy - R, yhi = cy + R;
        int xl = max(xlo, 0), xh = min(xhi, GG-1);
        int yl = max(ylo, 0), yh = min(yhi, GG-1);
        for (int yy = yl; yy <= yh; yy++) {
            if (yy == ylo || yy == yhi) {
                // full row of the ring: cells contiguous in memory
                int s = g_cellStart[yy*GG + xl];
                int e = g_cellStart[yy*GG + xh + 1];
                SCAN_RANGE(s, e)
            } else {
                if (xlo >= 0) {
                    int s = g_cellStart[yy*GG + xlo];
                    int e = g_cellStart[yy*GG + xlo + 1];
                    SCAN_RANGE(s, e)
                }
                if (xhi <= GG-1) {
                    int s = g_cellStart[yy*GG + xhi];
                    int e = g_cellStart[yy*GG + xhi + 1];
                    SCAN_RANGE(s, e)
                }
            }
        }
        bool full = (xlo <= 0 && ylo <= 0 && xhi >= GG-1 && yhi >= GG-1);
        float x0 = GMINF + xlo * HCELL, x1 = GMINF + (xhi + 1) * HCELL;
        float y0 = GMINF + ylo * HCELL, y1 = GMINF + (yhi + 1) * HCELL;
        float db = fminf(fminf(px - x0, x1 - px), fminf(py - y0, y1 - py));
        if (full || (db > 0.0f && db*db > key[15] + MARGIN)) break;
    }

    float* o  = outKnn + (size_t)q * 66;
    float* xo = g_X0p  + (size_t)q * 80;
    o[0] = px; o[1] = py; xo[0] = px; xo[1] = py;
#pragma unroll
    for (int n = 0; n < 16; n++) {
        int mi = id[n];
        float ax = mc[2*mi], ay = mc[2*mi+1];
        float vx = mv[2*mi], vy = mv[2*mi+1];
        o[2+4*n] = ax; o[3+4*n] = ay; o[4+4*n] = vx; o[5+4*n] = vy;
        xo[2+4*n] = ax; xo[3+4*n] = ay; xo[4+4*n] = vx; xo[5+4*n] = vy;
    }
#pragma unroll
    for (int c = 66; c < 80; c++) xo[c] = 0.0f;
}

// ---------------- GEMM with optional fused input BN+ReLU ----------------
// C[B,N] = act(A)[B,K] @ W[K,N] + bias. act = BN(scale,shift)+ReLU if BNIN.
template<int BN, int TN, bool BNIN>
__global__ void __launch_bounds__(256) gemm_kernel(
    const float* __restrict__ A, const float* __restrict__ W,
    const float* __restrict__ bias, float* __restrict__ C,
    int K, int N)
{
    constexpr int BM = 128, BK = 16, TM = 8;
    __shared__ float As[BK][BM];
    __shared__ float Ws[BK][BN];
    __shared__ float sSc[512];
    __shared__ float sSh[512];
    int tid = threadIdx.x;
    if (BNIN) {
        for (int i = tid; i < K; i += 256) { sSc[i] = g_scale[i]; sSh[i] = g_shift[i]; }
    }
    __syncthreads();

    int row0 = blockIdx.y * BM;
    int col0 = blockIdx.x * BN;
    int trow = tid >> 4, tcol = tid & 15;
    int r0 = trow * TM, c0 = tcol * TN;

    float acc[TM][TN];
#pragma unroll
    for (int i = 0; i < TM; i++)
#pragma unroll
        for (int j = 0; j < TN; j++) acc[i][j] = 0.0f;

    int arow  = tid >> 1;
    int akoff = (tid & 1) * 8;
    const float* Ap = A + (size_t)(row0 + arow) * K + akoff;
    int wr = tid >> 4;
    int wc = (tid & 15) * (BN / 16);

    for (int k0 = 0; k0 < K; k0 += BK) {
        float4 a0 = *(const float4*)(Ap + k0);
        float4 a1 = *(const float4*)(Ap + k0 + 4);
        if (BNIN) {
            int kg = k0 + akoff;
            a0.x = fmaxf(0.0f, fmaf(a0.x, sSc[kg+0], sSh[kg+0]));
            a0.y = fmaxf(0.0f, fmaf(a0.y, sSc[kg+1], sSh[kg+1]));
            a0.z = fmaxf(0.0f, fmaf(a0.z, sSc[kg+2], sSh[kg+2]));
            a0.w = fmaxf(0.0f, fmaf(a0.w, sSc[kg+3], sSh[kg+3]));
            a1.x = fmaxf(0.0f, fmaf(a1.x, sSc[kg+4], sSh[kg+4]));
            a1.y = fmaxf(0.0f, fmaf(a1.y, sSc[kg+5], sSh[kg+5]));
            a1.z = fmaxf(0.0f, fmaf(a1.z, sSc[kg+6], sSh[kg+6]));
            a1.w = fmaxf(0.0f, fmaf(a1.w, sSc[kg+7], sSh[kg+7]));
        }
        As[akoff+0][arow] = a0.x; As[akoff+1][arow] = a0.y;
        As[akoff+2][arow] = a0.z; As[akoff+3][arow] = a0.w;
        As[akoff+4][arow] = a1.x; As[akoff+5][arow] = a1.y;
        As[akoff+6][arow] = a1.z; As[akoff+7][arow] = a1.w;

        const float* Wp = W + (size_t)(k0 + wr) * N + col0 + wc;
        if (BN == 128) {
            *(float4*)&Ws[wr][wc]     = *(const float4*)(Wp);
            *(float4*)&Ws[wr][wc + 4] = *(const float4*)(Wp + 4);
        } else {
            *(float4*)&Ws[wr][wc]     = *(const float4*)(Wp);
        }
        __syncthreads();

#pragma unroll
        for (int kk = 0; kk < BK; kk++) {
            float a[TM], b[TN];
            *(float4*)&a[0] = *(float4*)&As[kk][r0];
            *(float4*)&a[4] = *(float4*)&As[kk][r0 + 4];
            *(float4*)&b[0] = *(float4*)&Ws[kk][c0];
            if (TN == 8) *(float4*)&b[4] = *(float4*)&Ws[kk][c0 + 4];
#pragma unroll
            for (int i = 0; i < TM; i++)
#pragma unroll
                for (int j = 0; j < TN; j++)
                    acc[i][j] = fmaf(a[i], b[j], acc[i][j]);
        }
        __syncthreads();
    }

    float bj[TN];
#pragma unroll
    for (int j = 0; j < TN; j++) bj[j] = __ldg(&bias[col0 + c0 + j]);
#pragma unroll
    for (int i = 0; i < TM; i++) {
        float* Cp = C + (size_t)(row0 + r0 + i) * N + col0 + c0;
#pragma unroll
        for (int j = 0; j < TN; j += 4) {
            float4 o;
            o.x = acc[i][j+0] + bj[j+0];
            o.y = acc[i][j+1] + bj[j+1];
            o.z = acc[i][j+2] + bj[j+2];
            o.w = acc[i][j+3] + bj[j+3];
            *(float4*)(Cp + j) = o;
        }
    }
}

// ---------------- BN statistics (deterministic two-stage) ----------------
__global__ void colstats_kernel(const float* __restrict__ X, int N) {
    int col = threadIdx.x;
    int rb  = blockIdx.x;
    const float* p = X + (size_t)rb * 128 * N + col;
    float s = 0.0f, q = 0.0f;
    for (int r = 0; r < 128; r++) {
        float v = p[(size_t)r * N];
        s += v;
        q = fmaf(v, v, q);
    }
    g_psum[rb * N + col] = s;
    g_psq [rb * N + col] = q;
}

__global__ void bnfin_kernel(const float* __restrict__ g, const float* __restrict__ be, int N) {
    int c = threadIdx.x;
    if (c >= N) return;
    double s = 0.0, q = 0.0;
    for (int rb = 0; rb < 256; rb++) { s += (double)g_psum[rb * N + c]; q += (double)g_psq[rb * N + c]; }
    double mean = s / (double)BB;
    double var  = q / (double)BB - mean * mean;
    float sc = g[c] * rsqrtf((float)var + 1e-5f);
    g_scale[c] = sc;
    g_shift[c] = be[c] - (float)mean * sc;
}

// ---------------- final layer 64 -> 2 (with fused BN5+ReLU) ----------------
__global__ void __launch_bounds__(256) layer6_kernel(
    const float* __restrict__ w6, const float* __restrict__ b6, float* __restrict__ out)
{
    __shared__ float w[128];
    __shared__ float sc[64], sh[64];
    __shared__ float bb2[2];
    int t = threadIdx.x;
    if (t < 128) w[t] = w6[t];
    if (t < 64) { sc[t] = g_scale[t]; sh[t] = g_shift[t]; }
    if (t < 2) bb2[t] = b6[t];
    __syncthreads();
    int r = blockIdx.x * blockDim.x + t;
    if (r >= BB) return;
    const float* x = g_X5 + (size_t)r * 64;
    float a0 = bb2[0], a1 = bb2[1];
#pragma unroll
    for (int k = 0; k < 64; k++) {
        float v = fmaxf(0.0f, fmaf(x[k], sc[k], sh[k]));
        a0 = fmaf(v, w[2*k],   a0);
        a1 = fmaf(v, w[2*k+1], a1);
    }
    out[2*r]   = a0;
    out[2*r+1] = a1;
}

// ---------------- launch ----------------
extern "C" void kernel_launch(void* const* d_in, const int* in_sizes, int n_in,
                              void* d_out, int out_size) {
    const float* pos = (const float*)d_in[0];
    const float* mc  = (const float*)d_in[1];
    const float* mv  = (const float*)d_in[2];
    const float* w1 = (const float*)d_in[3];  const float* b1 = (const float*)d_in[4];
    const float* w2 = (const float*)d_in[5];  const float* b2 = (const float*)d_in[6];
    const float* w3 = (const float*)d_in[7];  const float* b3 = (const float*)d_in[8];
    const float* w4 = (const float*)d_in[9];  const float* b4 = (const float*)d_in[10];
    const float* w5 = (const float*)d_in[11]; const float* b5 = (const float*)d_in[12];
    const float* w6 = (const float*)d_in[13]; const float* b6 = (const float*)d_in[14];
    const float* g1 = (const float*)d_in[15]; const float* be1 = (const float*)d_in[16];
    const float* g2 = (const float*)d_in[17]; const float* be2 = (const float*)d_in[18];
    const float* g3 = (const float*)d_in[19]; const float* be3 = (const float*)d_in[20];
    const float* g4 = (const float*)d_in[21]; const float* be4 = (const float*)d_in[22];
    const float* g5 = (const float*)d_in[23]; const float* be5 = (const float*)d_in[24];
    float* out = (float*)d_out;

    float *X0p, *X1, *X2, *X3, *X4, *W1p;
    cudaGetSymbolAddress((void**)&X0p, g_X0p);
    cudaGetSymbolAddress((void**)&X1,  g_X1);
    cudaGetSymbolAddress((void**)&X2,  g_X2);
    cudaGetSymbolAddress((void**)&X3,  g_X3);
    cudaGetSymbolAddress((void**)&X4,  g_X4);
    cudaGetSymbolAddress((void**)&W1p, g_W1p);
    float* X5;
    cudaGetSymbolAddress((void**)&X5,  g_X5);

    // grid build + KNN feature assembly
    zero_cells_kernel<<<(NCELL + 255) / 256, 256>>>();
    count_kernel<<<(MM + 255) / 256, 256>>>(mc);
    scan_kernel<<<1, 256>>>();
    scatter_kernel<<<(MM + 255) / 256, 256>>>(mc);
    padw1_kernel<<<(80*128 + 255) / 256, 256>>>(w1);
    knn_kernel<<<BB / 256, 256>>>(pos, mc, mv, out + (size_t)BB * 2);

    // L1: 80(pad of 66) -> 128
    gemm_kernel<128, 8, false><<<dim3(1, BB/128), 256>>>(X0p, W1p, b1, X1, 80, 128);
    colstats_kernel<<<BB/128, 128>>>(X1, 128);
    bnfin_kernel<<<1, 128>>>(g1, be1, 128);

    // L2: 128 -> 256 (BN1+ReLU fused into A load)
    gemm_kernel<128, 8, true><<<dim3(2, BB/128), 256>>>(X1, w2, b2, X2, 128, 256);
    colstats_kernel<<<BB/128, 256>>>(X2, 256);
    bnfin_kernel<<<1, 256>>>(g2, be2, 256);

    // L3: 256 -> 512
    gemm_kernel<128, 8, true><<<dim3(4, BB/128), 256>>>(X2, w3, b3, X3, 256, 512);
    colstats_kernel<<<BB/128, 512>>>(X3, 512);
    bnfin_kernel<<<1, 512>>>(g3, be3, 512);

    // L4: 512 -> 128
    gemm_kernel<128, 8, true><<<dim3(1, BB/128), 256>>>(X3, w4, b4, X4, 512, 128);
    colstats_kernel<<<BB/128, 128>>>(X4, 128);
    bnfin_kernel<<<1, 128>>>(g4, be4, 128);

    // L5: 128 -> 64
    gemm_kernel<64, 4, true><<<dim3(1, BB/128), 256>>>(X4, w5, b5, X5, 128, 64);
    colstats_kernel<<<BB/128, 64>>>(X5, 64);
    bnfin_kernel<<<1, 64>>>(g5, be5, 64);

    // L6: 64 -> 2 (BN5+ReLU fused), writes x to out[0 : 2B]
    layer6_kernel<<<BB / 256, 256>>>(w6, b6, out);
}